// round 2
// baseline (speedup 1.0000x reference)
#include <cuda_runtime.h>
#include <cstdint>
#include <math.h>

// ---------------------------------------------------------------------------
// LSTM cell: gates = concat(h_t, x) @ concat(W_f,W_i,W_c,W_o) + b   [8192 x 4096]
// then f,i = sigmoid, c~ = tanh, o = sigmoid; c_new = f*c_t + i*c~; h = o*tanh(c_new)
// Output layout: [h_new, h_new, c_new] (3 * B * H floats)
//
// GEMM: M=8192, K=2048, N=4096, TF32 mma.sync m16n8k8, cp.async double buffer.
// ---------------------------------------------------------------------------

namespace {
constexpr int Bsz = 8192;
constexpr int Hsz = 1024;
constexpr int Ksz = 2048;
constexpr int Nsz = 4096;

constexpr int BM = 128, BN = 128, BK = 32;
constexpr int LDA = BK + 4;        // 36 floats (pad keeps 16B alignment, kills conflicts)
constexpr int LDB = BN + 8;        // 136 floats (g + 8*tg covers 32 banks -> conflict free)
constexpr int A_STRIDE = BM * LDA; // 4608 floats per buffer
constexpr int B_STRIDE = BK * LDB; // 4352 floats per buffer
constexpr int SMEM_FLOATS = 2 * A_STRIDE + 2 * B_STRIDE;
constexpr int SMEM_BYTES = SMEM_FLOATS * 4;  // 71680 B
}

// Scratch for pre-activation gates (no cudaMalloc allowed -> device global).
__device__ float g_gates[(size_t)Bsz * Nsz];

__device__ __forceinline__ void cp16(float* smem_dst, const float* gsrc) {
    uint32_t s = (uint32_t)__cvta_generic_to_shared(smem_dst);
    asm volatile("cp.async.cg.shared.global [%0], [%1], 16;" :: "r"(s), "l"(gsrc));
}

__device__ __forceinline__ uint32_t f2tf(float f) {
    uint32_t r;
    asm("cvt.rna.tf32.f32 %0, %1;" : "=r"(r) : "f"(f));
    return r;
}

__device__ __forceinline__ void mma_tf32(float* c, const uint32_t* a, const uint32_t* b) {
    asm volatile(
        "mma.sync.aligned.m16n8k8.row.col.f32.tf32.tf32.f32 "
        "{%0,%1,%2,%3}, {%4,%5,%6,%7}, {%8,%9}, {%0,%1,%2,%3};"
        : "+f"(c[0]), "+f"(c[1]), "+f"(c[2]), "+f"(c[3])
        : "r"(a[0]), "r"(a[1]), "r"(a[2]), "r"(a[3]), "r"(b[0]), "r"(b[1]));
}

__device__ __forceinline__ void prefetch_tiles(
    float* smem, int buf, const float* Abase, const float* Bbase, int tid, int m0)
{
    float* As  = smem + buf * A_STRIDE;
    float* Bsm = smem + 2 * A_STRIDE + buf * B_STRIDE;
    // A tile: 128 rows x 32 floats = 1024 float4 loads (4/thread @ 256 threads)
    #pragma unroll
    for (int it = 0; it < 4; ++it) {
        int lin = tid + it * 256;
        int r = lin >> 3, q = lin & 7;
        cp16(&As[r * LDA + q * 4], Abase + (size_t)(m0 + r) * 1024 + q * 4);
    }
    // B tile: 32 rows x 128 floats = 1024 float4 loads
    #pragma unroll
    for (int it = 0; it < 4; ++it) {
        int lin = tid + it * 256;
        int r = lin >> 5, q = lin & 31;
        cp16(&Bsm[r * LDB + q * 4], Bbase + (size_t)r * 1024 + q * 4);
    }
    asm volatile("cp.async.commit_group;");
}

__global__ __launch_bounds__(256, 2)
void lstm_gemm(const float* __restrict__ h_t, const float* __restrict__ x,
               const float* __restrict__ Wf, const float* __restrict__ Wi,
               const float* __restrict__ Wc, const float* __restrict__ Wo)
{
    extern __shared__ float smem[];
    const int tid = threadIdx.x;
    const int m0 = blockIdx.y * BM;
    const int n0 = blockIdx.x * BN;

    // Each N-tile of 128 lies inside exactly one gate (1024 % 128 == 0).
    const int gate = n0 >> 10;
    const float* W = (gate == 0) ? Wf : (gate == 1) ? Wi : (gate == 2) ? Wc : Wo;
    const int col0 = n0 & 1023;

    const int warp = tid >> 5, lane = tid & 31;
    const int wm = warp >> 2, wn = warp & 3;   // 2 x 4 warp grid
    const int rb = wm * 64, cb = wn * 32;      // warp tile 64 x 32
    const int g = lane >> 2, tg = lane & 3;

    float acc[4][4][4];
    #pragma unroll
    for (int i = 0; i < 4; ++i)
        #pragma unroll
        for (int j = 0; j < 4; ++j)
            #pragma unroll
            for (int t = 0; t < 4; ++t)
                acc[i][j][t] = 0.f;

    const int KT = Ksz / BK;  // 64 k-tiles; each lies wholly in h_t or x (1024 % 32 == 0)
    {
        const float* Ab = h_t;  // k0 = 0 < 1024
        prefetch_tiles(smem, 0, Ab, W + (size_t)0 * 1024 + col0, tid, m0);
    }

    int buf = 0;
    for (int kt = 0; kt < KT; ++kt) {
        asm volatile("cp.async.wait_group 0;");
        __syncthreads();
        if (kt + 1 < KT) {
            const int k1 = (kt + 1) * BK;
            const float* Ab = (k1 < 1024) ? (h_t + k1) : (x + (k1 - 1024));
            prefetch_tiles(smem, buf ^ 1, Ab, W + (size_t)k1 * 1024 + col0, tid, m0);
        }
        const float* As  = smem + buf * A_STRIDE;
        const float* Bsm = smem + 2 * A_STRIDE + buf * B_STRIDE;

        #pragma unroll
        for (int kk = 0; kk < BK; kk += 8) {
            uint32_t aF[4][4];
            #pragma unroll
            for (int i = 0; i < 4; ++i) {
                const int r0 = rb + i * 16 + g;
                aF[i][0] = f2tf(As[r0 * LDA + kk + tg]);
                aF[i][1] = f2tf(As[(r0 + 8) * LDA + kk + tg]);
                aF[i][2] = f2tf(As[r0 * LDA + kk + tg + 4]);
                aF[i][3] = f2tf(As[(r0 + 8) * LDA + kk + tg + 4]);
            }
            uint32_t bF[4][2];
            #pragma unroll
            for (int j = 0; j < 4; ++j) {
                const int c0 = cb + j * 8 + g;
                bF[j][0] = f2tf(Bsm[(kk + tg) * LDB + c0]);
                bF[j][1] = f2tf(Bsm[(kk + tg + 4) * LDB + c0]);
            }
            #pragma unroll
            for (int i = 0; i < 4; ++i)
                #pragma unroll
                for (int j = 0; j < 4; ++j)
                    mma_tf32(acc[i][j], aF[i], bF[j]);
        }
        __syncthreads();
        buf ^= 1;
    }

    // Store pre-activation gates.
    #pragma unroll
    for (int i = 0; i < 4; ++i) {
        const int row = m0 + rb + i * 16 + g;
        #pragma unroll
        for (int j = 0; j < 4; ++j) {
            const int col = n0 + cb + j * 8 + tg * 2;
            *reinterpret_cast<float2*>(&g_gates[(size_t)row * Nsz + col]) =
                make_float2(acc[i][j][0], acc[i][j][1]);
            *reinterpret_cast<float2*>(&g_gates[(size_t)(row + 8) * Nsz + col]) =
                make_float2(acc[i][j][2], acc[i][j][3]);
        }
    }
}

__device__ __forceinline__ float sigf(float v) { return 1.f / (1.f + __expf(-v)); }

__global__ __launch_bounds__(256)
void lstm_epilogue(const float* __restrict__ c_t,
                   const float* __restrict__ bf, const float* __restrict__ bi,
                   const float* __restrict__ bc, const float* __restrict__ bo,
                   float* __restrict__ out, int nchunks)
{
    const int idx = blockIdx.x * blockDim.x + threadIdx.x;
    const int total = Bsz * Hsz / 4;
    if (idx >= total) return;
    const int row = idx >> 8;          // H/4 = 256 float4 per row
    const int c4  = idx & 255;
    const int col = c4 * 4;

    const float4* gp = reinterpret_cast<const float4*>(g_gates + (size_t)row * Nsz);
    float4 vf = gp[c4];
    float4 vi = gp[256 + c4];
    float4 vc = gp[512 + c4];
    float4 vo = gp[768 + c4];

    const float4 bbf = *reinterpret_cast<const float4*>(bf + col);
    const float4 bbi = *reinterpret_cast<const float4*>(bi + col);
    const float4 bbc = *reinterpret_cast<const float4*>(bc + col);
    const float4 bbo = *reinterpret_cast<const float4*>(bo + col);
    const float4 ct  = *reinterpret_cast<const float4*>(c_t + (size_t)row * Hsz + col);

    float hh[4], cn[4];
    const float fx[4] = {vf.x + bbf.x, vf.y + bbf.y, vf.z + bbf.z, vf.w + bbf.w};
    const float ix[4] = {vi.x + bbi.x, vi.y + bbi.y, vi.z + bbi.z, vi.w + bbi.w};
    const float cx[4] = {vc.x + bbc.x, vc.y + bbc.y, vc.z + bbc.z, vc.w + bbc.w};
    const float ox[4] = {vo.x + bbo.x, vo.y + bbo.y, vo.z + bbo.z, vo.w + bbo.w};
    const float ctv[4] = {ct.x, ct.y, ct.z, ct.w};
    #pragma unroll
    for (int t = 0; t < 4; ++t) {
        const float f = sigf(fx[t]);
        const float i = sigf(ix[t]);
        const float cc = tanhf(cx[t]);
        const float o = sigf(ox[t]);
        cn[t] = f * ctv[t] + i * cc;
        hh[t] = o * tanhf(cn[t]);
    }

    const size_t BH = (size_t)Bsz * Hsz;
    const size_t off = (size_t)row * Hsz + col;
    const float4 hv = make_float4(hh[0], hh[1], hh[2], hh[3]);
    const float4 cv = make_float4(cn[0], cn[1], cn[2], cn[3]);
    // chunks 0..n-2 get h_new, last chunk gets c_new
    for (int ch = 0; ch < nchunks - 1; ++ch)
        *reinterpret_cast<float4*>(out + (size_t)ch * BH + off) = hv;
    *reinterpret_cast<float4*>(out + (size_t)(nchunks - 1) * BH + off) =
        (nchunks > 1) ? cv : hv;
}

extern "C" void kernel_launch(void* const* d_in, const int* in_sizes, int n_in,
                              void* d_out, int out_size)
{
    const float* x   = (const float*)d_in[0];
    const float* h_t = (const float*)d_in[1];
    const float* c_t = (const float*)d_in[2];
    const float* Wf  = (const float*)d_in[3];
    const float* bf  = (const float*)d_in[4];
    const float* Wi  = (const float*)d_in[5];
    const float* bi  = (const float*)d_in[6];
    const float* Wc  = (const float*)d_in[7];
    const float* bc  = (const float*)d_in[8];
    const float* Wo  = (const float*)d_in[9];
    const float* bo  = (const float*)d_in[10];

    cudaFuncSetAttribute(lstm_gemm, cudaFuncAttributeMaxDynamicSharedMemorySize, SMEM_BYTES);

    dim3 grid(Nsz / BN, Bsz / BM);   // 32 x 64
    lstm_gemm<<<grid, 256, SMEM_BYTES>>>(h_t, x, Wf, Wi, Wc, Wo);

    int nchunks = out_size / (Bsz * Hsz);
    if (nchunks < 1) nchunks = 1;
    const int total = Bsz * Hsz / 4;
    lstm_epilogue<<<(total + 255) / 256, 256>>>(c_t, bf, bi, bc, bo, (float*)d_out, nchunks);
}

// round 10
// speedup vs baseline: 1.0969x; 1.0969x over previous
#include <cuda_runtime.h>
#include <cstdint>
#include <math.h>

// ===========================================================================
// LSTM cell, legacy tensor path (sm_100 target has no tcgen05).
//   Prepass: round A=concat(h_t,x) and W=[4][K][H] to tf32 in gmem.
//   GEMM: TF32 mma.sync m16n8k8, cp.async double buffer. CTA tile:
//   128 rows x (4 gates x 32 H-cols). No cvt in hot loop (data pre-rounded).
//   Epilogue fused: each thread owns f,i,c~,o for its (row,col) -> h,c out.
// ===========================================================================

namespace {
constexpr int Bsz = 8192, Hsz = 1024, Ksz = 2048;
constexpr int BM = 128, BK = 32;
constexpr int LDA = BK + 4;          // 36
constexpr int LDB = 128 + 8;         // 136
constexpr int A_STRIDE = BM * LDA;   // 4608 floats
constexpr int B_STRIDE = BK * LDB;   // 4352 floats
constexpr int SMEM_FLOATS = 2 * A_STRIDE + 2 * B_STRIDE;
constexpr int SMEM_BYTES = SMEM_FLOATS * 4;   // 71680

constexpr size_t A_ELEMS = (size_t)Bsz * Ksz;   // 16M
constexpr size_t W_ELEMS = 4ull * Ksz * Hsz;    // 8M
}

__device__ float g_A[A_ELEMS];   // tf32-rounded concat(h_t, x), [B][K]
__device__ float g_W[W_ELEMS];   // tf32-rounded weights [gate][K][H]

__device__ __forceinline__ void cp16(float* smem_dst, const float* gsrc) {
    uint32_t s = (uint32_t)__cvta_generic_to_shared(smem_dst);
    asm volatile("cp.async.cg.shared.global [%0], [%1], 16;" :: "r"(s), "l"(gsrc));
}
__device__ __forceinline__ uint32_t f2tf(float f) {
    uint32_t r; asm("cvt.rna.tf32.f32 %0, %1;" : "=r"(r) : "f"(f)); return r;
}
__device__ __forceinline__ void mma_tf32(float* c, const uint32_t* a, const uint32_t* b) {
    asm volatile(
        "mma.sync.aligned.m16n8k8.row.col.f32.tf32.tf32.f32 "
        "{%0,%1,%2,%3}, {%4,%5,%6,%7}, {%8,%9}, {%0,%1,%2,%3};"
        : "+f"(c[0]), "+f"(c[1]), "+f"(c[2]), "+f"(c[3])
        : "r"(a[0]), "r"(a[1]), "r"(a[2]), "r"(a[3]), "r"(b[0]), "r"(b[1]));
}
__device__ __forceinline__ float sigf(float v) { return 1.f / (1.f + __expf(-v)); }

// ---------------------------------------------------------------------------
// Prepass: tf32-round inputs; pack A=[h|x] row-major, W=[4][K][H].
__global__ __launch_bounds__(256)
void lstm_prepass(const float* __restrict__ h_t, const float* __restrict__ x,
                  const float* __restrict__ Wf, const float* __restrict__ Wi,
                  const float* __restrict__ Wc, const float* __restrict__ Wo)
{
    const size_t i4 = (size_t)blockIdx.x * 256 + threadIdx.x;
    const size_t A4 = A_ELEMS / 4, T4 = (A_ELEMS + W_ELEMS) / 4;
    if (i4 >= T4) return;
    float4 v; float4* dst;
    if (i4 < A4) {
        const size_t e = i4 * 4;
        const int m = (int)(e >> 11), k = (int)(e & 2047);
        const float* src = (k < 1024) ? (h_t + (size_t)m * 1024 + k)
                                      : (x + (size_t)m * 1024 + (k - 1024));
        v = *reinterpret_cast<const float4*>(src);
        dst = reinterpret_cast<float4*>(g_A + e);
    } else {
        const size_t w = (i4 - A4) * 4;
        const int g = (int)(w >> 21);            // Ksz*Hsz = 2^21
        const size_t r = w & ((1u << 21) - 1);
        const float* W = (g == 0) ? Wf : (g == 1) ? Wi : (g == 2) ? Wc : Wo;
        v = *reinterpret_cast<const float4*>(W + r);
        dst = reinterpret_cast<float4*>(g_W + w);
    }
    v.x = __uint_as_float(f2tf(v.x)); v.y = __uint_as_float(f2tf(v.y));
    v.z = __uint_as_float(f2tf(v.z)); v.w = __uint_as_float(f2tf(v.w));
    *dst = v;
}

// ---------------------------------------------------------------------------
__device__ __forceinline__ void prefetch_tiles(float* smem, int buf, int k0,
                                               int m0, int h0, int tid)
{
    float* As  = smem + buf * A_STRIDE;
    float* Bsm = smem + 2 * A_STRIDE + buf * B_STRIDE;
    #pragma unroll
    for (int it = 0; it < 4; ++it) {            // A: 128 x 32 floats
        const int lin = tid + it * 256;
        const int r = lin >> 3, q = lin & 7;
        cp16(&As[r * LDA + q * 4], g_A + (size_t)(m0 + r) * Ksz + k0 + q * 4);
    }
    #pragma unroll
    for (int it = 0; it < 4; ++it) {            // B: 32 rows x 128 cols (4 gates x 32)
        const int lin = tid + it * 256;
        const int r = lin >> 5, q = lin & 31;
        const int col0 = q * 4;
        const int gate = col0 >> 5, hc = col0 & 31;
        cp16(&Bsm[r * LDB + col0],
             g_W + (size_t)gate * (Ksz * Hsz) + (size_t)(k0 + r) * Hsz + h0 + hc);
    }
    asm volatile("cp.async.commit_group;");
}

__global__ __launch_bounds__(256, 2)
void lstm_gemm_fused(const float* __restrict__ c_t,
                     const float* __restrict__ bfp, const float* __restrict__ bip,
                     const float* __restrict__ bcp, const float* __restrict__ bop,
                     float* __restrict__ out, int nchunks)
{
    extern __shared__ float smem[];
    const int tid = threadIdx.x;
    const int m0 = blockIdx.y * BM;
    const int h0 = blockIdx.x * 32;            // 32 H-cols per CTA, all 4 gates

    const int warp = tid >> 5, lane = tid & 31;
    const int wm = warp >> 2, wn = warp & 3;   // 2 x 4 warps
    const int rb = wm * 64;                     // warp rows
    const int g = lane >> 2, tg = lane & 3;

    // acc[m-frag][gate][4]
    float acc[4][4][4];
    #pragma unroll
    for (int i = 0; i < 4; ++i)
        #pragma unroll
        for (int j = 0; j < 4; ++j)
            #pragma unroll
            for (int t = 0; t < 4; ++t) acc[i][j][t] = 0.f;

    const int KT = Ksz / BK;   // 64
    prefetch_tiles(smem, 0, 0, m0, h0, tid);

    int buf = 0;
    for (int kt = 0; kt < KT; ++kt) {
        asm volatile("cp.async.wait_group 0;");
        __syncthreads();
        if (kt + 1 < KT)
            prefetch_tiles(smem, buf ^ 1, (kt + 1) * BK, m0, h0, tid);

        const float* As  = smem + buf * A_STRIDE;
        const float* Bsm = smem + 2 * A_STRIDE + buf * B_STRIDE;

        #pragma unroll
        for (int kk = 0; kk < BK; kk += 8) {
            uint32_t aF[4][4];
            #pragma unroll
            for (int i = 0; i < 4; ++i) {
                const int r0 = rb + i * 16 + g;
                aF[i][0] = __float_as_uint(As[r0 * LDA + kk + tg]);
                aF[i][1] = __float_as_uint(As[(r0 + 8) * LDA + kk + tg]);
                aF[i][2] = __float_as_uint(As[r0 * LDA + kk + tg + 4]);
                aF[i][3] = __float_as_uint(As[(r0 + 8) * LDA + kk + tg + 4]);
            }
            uint32_t bF[4][2];
            #pragma unroll
            for (int gate = 0; gate < 4; ++gate) {
                const int c0 = gate * 32 + wn * 8 + g;
                bF[gate][0] = __float_as_uint(Bsm[(kk + tg) * LDB + c0]);
                bF[gate][1] = __float_as_uint(Bsm[(kk + tg + 4) * LDB + c0]);
            }
            #pragma unroll
            for (int i = 0; i < 4; ++i)
                #pragma unroll
                for (int gate = 0; gate < 4; ++gate)
                    mma_tf32(acc[i][gate], aF[i], bF[gate]);
        }
        __syncthreads();
        buf ^= 1;
    }

    // ---- fused epilogue ----
    const int colg = h0 + wn * 8 + tg * 2;      // global H col (pair)
    const float2 bF2 = *reinterpret_cast<const float2*>(bfp + colg);
    const float2 bI2 = *reinterpret_cast<const float2*>(bip + colg);
    const float2 bC2 = *reinterpret_cast<const float2*>(bcp + colg);
    const float2 bO2 = *reinterpret_cast<const float2*>(bop + colg);
    const size_t BH = (size_t)Bsz * Hsz;

    #pragma unroll
    for (int i = 0; i < 4; ++i) {
        #pragma unroll
        for (int half = 0; half < 2; ++half) {
            const int row = m0 + rb + i * 16 + g + half * 8;
            const int t0 = half * 2;            // acc regs {t0, t0+1} = cols colg, colg+1
            const float2 ct2 =
                *reinterpret_cast<const float2*>(c_t + (size_t)row * Hsz + colg);
            float hv[2], cv[2];
            #pragma unroll
            for (int u = 0; u < 2; ++u) {
                const float fpre = acc[i][0][t0 + u] + ((u == 0) ? bF2.x : bF2.y);
                const float ipre = acc[i][1][t0 + u] + ((u == 0) ? bI2.x : bI2.y);
                const float cpre = acc[i][2][t0 + u] + ((u == 0) ? bC2.x : bC2.y);
                const float opre = acc[i][3][t0 + u] + ((u == 0) ? bO2.x : bO2.y);
                const float fv = sigf(fpre);
                const float iv = sigf(ipre);
                const float gv = tanhf(cpre);
                const float ov = sigf(opre);
                const float ctv = (u == 0) ? ct2.x : ct2.y;
                cv[u] = fv * ctv + iv * gv;
                hv[u] = ov * tanhf(cv[u]);
            }
            const size_t off = (size_t)row * Hsz + colg;
            const float2 h2 = make_float2(hv[0], hv[1]);
            const float2 c2 = make_float2(cv[0], cv[1]);
            for (int ch = 0; ch < nchunks - 1; ++ch)
                *reinterpret_cast<float2*>(out + (size_t)ch * BH + off) = h2;
            *reinterpret_cast<float2*>(out + (size_t)(nchunks - 1) * BH + off) =
                (nchunks > 1) ? c2 : h2;
        }
    }
}

// ---------------------------------------------------------------------------
extern "C" void kernel_launch(void* const* d_in, const int* in_sizes, int n_in,
                              void* d_out, int out_size)
{
    const float* x   = (const float*)d_in[0];
    const float* h_t = (const float*)d_in[1];
    const float* c_t = (const float*)d_in[2];
    const float* Wf  = (const float*)d_in[3];
    const float* bf  = (const float*)d_in[4];
    const float* Wi  = (const float*)d_in[5];
    const float* bi  = (const float*)d_in[6];
    const float* Wc  = (const float*)d_in[7];
    const float* bc  = (const float*)d_in[8];
    const float* Wo  = (const float*)d_in[9];
    const float* bo  = (const float*)d_in[10];

    cudaFuncSetAttribute(lstm_gemm_fused, cudaFuncAttributeMaxDynamicSharedMemorySize,
                         SMEM_BYTES);

    const size_t T4 = (A_ELEMS + W_ELEMS) / 4;
    lstm_prepass<<<(unsigned)((T4 + 255) / 256), 256>>>(h_t, x, Wf, Wi, Wc, Wo);

    int nchunks = out_size / (Bsz * Hsz);
    if (nchunks < 1) nchunks = 1;
    dim3 grid(Hsz / 32, Bsz / BM);   // 32 x 64 = 2048 CTAs
    lstm_gemm_fused<<<grid, 256, SMEM_BYTES>>>(c_t, bf, bi, bc, bo,
                                               (float*)d_out, nchunks);
}

// round 12
// speedup vs baseline: 1.1213x; 1.0222x over previous
#include <cuda_runtime.h>
#include <cstdint>
#include <math.h>

// ===========================================================================
// LSTM cell, legacy tensor path (sm_100 target: no tcgen05).
//   Prepass: round A=concat(h_t,x) and W=[4][K][H] to tf32 in gmem.
//   GEMM: TF32 mma.sync m16n8k8, 3-stage cp.async pipeline.
//   Sync per chunk: wait_group 1 -> __syncthreads -> prefetch(kt+2) -> consume.
//   (RAW: barrier AFTER wait publishes all threads' copies. WAR: consume(kt-1)
//    precedes barrier(kt), so prefetch into stage (kt+2)%3 is safe.)
//   CTA tile: 128 rows x (4 gates x 32 H-cols); fused LSTM epilogue.
// ===========================================================================

namespace {
constexpr int Bsz = 8192, Hsz = 1024, Ksz = 2048;
constexpr int BM = 128, BK = 32;
constexpr int LDA = BK + 4;          // 36
constexpr int LDB = 128 + 8;         // 136
constexpr int A_STRIDE = BM * LDA;   // 4608 floats
constexpr int B_STRIDE = BK * LDB;   // 4352 floats
constexpr int NSTAGE = 3;
constexpr int SMEM_FLOATS = NSTAGE * (A_STRIDE + B_STRIDE);   // 26880
constexpr int SMEM_BYTES = SMEM_FLOATS * 4;                   // 107520

constexpr size_t A_ELEMS = (size_t)Bsz * Ksz;   // 16M
constexpr size_t W_ELEMS = 4ull * Ksz * Hsz;    // 8M
}

__device__ float g_A[A_ELEMS];   // tf32-rounded concat(h_t, x), [B][K]
__device__ float g_W[W_ELEMS];   // tf32-rounded weights [gate][K][H]

__device__ __forceinline__ void cp16(float* smem_dst, const float* gsrc) {
    uint32_t s = (uint32_t)__cvta_generic_to_shared(smem_dst);
    asm volatile("cp.async.cg.shared.global [%0], [%1], 16;" :: "r"(s), "l"(gsrc));
}
__device__ __forceinline__ uint32_t f2tf(float f) {
    uint32_t r; asm("cvt.rna.tf32.f32 %0, %1;" : "=r"(r) : "f"(f)); return r;
}
__device__ __forceinline__ void mma_tf32(float* c, const uint32_t* a, const uint32_t* b) {
    asm volatile(
        "mma.sync.aligned.m16n8k8.row.col.f32.tf32.tf32.f32 "
        "{%0,%1,%2,%3}, {%4,%5,%6,%7}, {%8,%9}, {%0,%1,%2,%3};"
        : "+f"(c[0]), "+f"(c[1]), "+f"(c[2]), "+f"(c[3])
        : "r"(a[0]), "r"(a[1]), "r"(a[2]), "r"(a[3]), "r"(b[0]), "r"(b[1]));
}
__device__ __forceinline__ float sigf(float v) { return 1.f / (1.f + __expf(-v)); }

// ---------------------------------------------------------------------------
__global__ __launch_bounds__(256)
void lstm_prepass(const float* __restrict__ h_t, const float* __restrict__ x,
                  const float* __restrict__ Wf, const float* __restrict__ Wi,
                  const float* __restrict__ Wc, const float* __restrict__ Wo)
{
    const size_t i4 = (size_t)blockIdx.x * 256 + threadIdx.x;
    const size_t A4 = A_ELEMS / 4, T4 = (A_ELEMS + W_ELEMS) / 4;
    if (i4 >= T4) return;
    float4 v; float4* dst;
    if (i4 < A4) {
        const size_t e = i4 * 4;
        const int m = (int)(e >> 11), k = (int)(e & 2047);
        const float* src = (k < 1024) ? (h_t + (size_t)m * 1024 + k)
                                      : (x + (size_t)m * 1024 + (k - 1024));
        v = *reinterpret_cast<const float4*>(src);
        dst = reinterpret_cast<float4*>(g_A + e);
    } else {
        const size_t w = (i4 - A4) * 4;
        const int g = (int)(w >> 21);            // Ksz*Hsz = 2^21
        const size_t r = w & ((1u << 21) - 1);
        const float* W = (g == 0) ? Wf : (g == 1) ? Wi : (g == 2) ? Wc : Wo;
        v = *reinterpret_cast<const float4*>(W + r);
        dst = reinterpret_cast<float4*>(g_W + w);
    }
    v.x = __uint_as_float(f2tf(v.x)); v.y = __uint_as_float(f2tf(v.y));
    v.z = __uint_as_float(f2tf(v.z)); v.w = __uint_as_float(f2tf(v.w));
    *dst = v;
}

// ---------------------------------------------------------------------------
__device__ __forceinline__ void prefetch_tiles(float* smem, int stage, int k0,
                                               int m0, int h0, int tid)
{
    float* As  = smem + stage * A_STRIDE;
    float* Bsm = smem + NSTAGE * A_STRIDE + stage * B_STRIDE;
    #pragma unroll
    for (int it = 0; it < 4; ++it) {            // A: 128 rows x 32 floats
        const int lin = tid + it * 256;
        const int r = lin >> 3, q = lin & 7;
        cp16(&As[r * LDA + q * 4], g_A + (size_t)(m0 + r) * Ksz + k0 + q * 4);
    }
    #pragma unroll
    for (int it = 0; it < 4; ++it) {            // B: 32 rows x 128 cols (4 gates x 32)
        const int lin = tid + it * 256;
        const int r = lin >> 5, q = lin & 31;
        const int col0 = q * 4;
        const int gate = col0 >> 5, hc = col0 & 31;
        cp16(&Bsm[r * LDB + col0],
             g_W + (size_t)gate * (Ksz * Hsz) + (size_t)(k0 + r) * Hsz + h0 + hc);
    }
    asm volatile("cp.async.commit_group;");
}

__global__ __launch_bounds__(256, 2)
void lstm_gemm_fused(const float* __restrict__ c_t,
                     const float* __restrict__ bfp, const float* __restrict__ bip,
                     const float* __restrict__ bcp, const float* __restrict__ bop,
                     float* __restrict__ out, int nchunks)
{
    extern __shared__ float smem[];
    const int tid = threadIdx.x;
    const int m0 = blockIdx.y * BM;
    const int h0 = blockIdx.x * 32;            // 32 H-cols per CTA, all 4 gates

    const int warp = tid >> 5, lane = tid & 31;
    const int wm = warp >> 2, wn = warp & 3;   // 2 x 4 warps
    const int rb = wm * 64;
    const int g = lane >> 2, tg = lane & 3;

    float acc[4][4][4];                        // [m-frag][gate][reg]
    #pragma unroll
    for (int i = 0; i < 4; ++i)
        #pragma unroll
        for (int j = 0; j < 4; ++j)
            #pragma unroll
            for (int t = 0; t < 4; ++t) acc[i][j][t] = 0.f;

    const int KT = Ksz / BK;   // 64
    prefetch_tiles(smem, 0, 0, m0, h0, tid);
    prefetch_tiles(smem, 1, BK, m0, h0, tid);

    int stage = 0;
    for (int kt = 0; kt < KT; ++kt) {
        // RAW: group kt must be complete in EVERY thread, then publish via barrier.
        if (kt + 1 < KT) asm volatile("cp.async.wait_group 1;");
        else             asm volatile("cp.async.wait_group 0;");
        __syncthreads();
        // WAR-safe: stage (kt+2)%3 was last read at iter kt-1, before this barrier.
        if (kt + 2 < KT)
            prefetch_tiles(smem, (stage + 2) % NSTAGE, (kt + 2) * BK, m0, h0, tid);

        const float* As  = smem + stage * A_STRIDE;
        const float* Bsm = smem + NSTAGE * A_STRIDE + stage * B_STRIDE;

        #pragma unroll
        for (int kk = 0; kk < BK; kk += 8) {
            uint32_t aF[4][4];
            #pragma unroll
            for (int i = 0; i < 4; ++i) {
                const int r0 = rb + i * 16 + g;
                aF[i][0] = __float_as_uint(As[r0 * LDA + kk + tg]);
                aF[i][1] = __float_as_uint(As[(r0 + 8) * LDA + kk + tg]);
                aF[i][2] = __float_as_uint(As[r0 * LDA + kk + tg + 4]);
                aF[i][3] = __float_as_uint(As[(r0 + 8) * LDA + kk + tg + 4]);
            }
            uint32_t bF[4][2];
            #pragma unroll
            for (int gate = 0; gate < 4; ++gate) {
                const int c0 = gate * 32 + wn * 8 + g;
                bF[gate][0] = __float_as_uint(Bsm[(kk + tg) * LDB + c0]);
                bF[gate][1] = __float_as_uint(Bsm[(kk + tg + 4) * LDB + c0]);
            }
            #pragma unroll
            for (int i = 0; i < 4; ++i)
                #pragma unroll
                for (int gate = 0; gate < 4; ++gate)
                    mma_tf32(acc[i][gate], aF[i], bF[gate]);
        }
        stage = (stage + 1) % NSTAGE;
    }

    // ---- fused epilogue ----
    const int colg = h0 + wn * 8 + tg * 2;
    const float2 bF2 = *reinterpret_cast<const float2*>(bfp + colg);
    const float2 bI2 = *reinterpret_cast<const float2*>(bip + colg);
    const float2 bC2 = *reinterpret_cast<const float2*>(bcp + colg);
    const float2 bO2 = *reinterpret_cast<const float2*>(bop + colg);
    const size_t BH = (size_t)Bsz * Hsz;

    #pragma unroll
    for (int i = 0; i < 4; ++i) {
        #pragma unroll
        for (int half = 0; half < 2; ++half) {
            const int row = m0 + rb + i * 16 + g + half * 8;
            const int t0 = half * 2;
            const float2 ct2 =
                *reinterpret_cast<const float2*>(c_t + (size_t)row * Hsz + colg);
            float hv[2], cv[2];
            #pragma unroll
            for (int u = 0; u < 2; ++u) {
                const float fpre = acc[i][0][t0 + u] + ((u == 0) ? bF2.x : bF2.y);
                const float ipre = acc[i][1][t0 + u] + ((u == 0) ? bI2.x : bI2.y);
                const float cpre = acc[i][2][t0 + u] + ((u == 0) ? bC2.x : bC2.y);
                const float opre = acc[i][3][t0 + u] + ((u == 0) ? bO2.x : bO2.y);
                const float fv = sigf(fpre);
                const float iv = sigf(ipre);
                const float gv = tanhf(cpre);
                const float ov = sigf(opre);
                const float ctv = (u == 0) ? ct2.x : ct2.y;
                cv[u] = fv * ctv + iv * gv;
                hv[u] = ov * tanhf(cv[u]);
            }
            const size_t off = (size_t)row * Hsz + colg;
            const float2 h2 = make_float2(hv[0], hv[1]);
            const float2 c2 = make_float2(cv[0], cv[1]);
            for (int ch = 0; ch < nchunks - 1; ++ch)
                *reinterpret_cast<float2*>(out + (size_t)ch * BH + off) = h2;
            *reinterpret_cast<float2*>(out + (size_t)(nchunks - 1) * BH + off) =
                (nchunks > 1) ? c2 : h2;
        }
    }
}

// ---------------------------------------------------------------------------
extern "C" void kernel_launch(void* const* d_in, const int* in_sizes, int n_in,
                              void* d_out, int out_size)
{
    const float* x   = (const float*)d_in[0];
    const float* h_t = (const float*)d_in[1];
    const float* c_t = (const float*)d_in[2];
    const float* Wf  = (const float*)d_in[3];
    const float* bf  = (const float*)d_in[4];
    const float* Wi  = (const float*)d_in[5];
    const float* bi  = (const float*)d_in[6];
    const float* Wc  = (const float*)d_in[7];
    const float* bc  = (const float*)d_in[8];
    const float* Wo  = (const float*)d_in[9];
    const float* bo  = (const float*)d_in[10];

    cudaFuncSetAttribute(lstm_gemm_fused, cudaFuncAttributeMaxDynamicSharedMemorySize,
                         SMEM_BYTES);

    const size_t T4 = (A_ELEMS + W_ELEMS) / 4;
    lstm_prepass<<<(unsigned)((T4 + 255) / 256), 256>>>(h_t, x, Wf, Wi, Wc, Wo);

    int nchunks = out_size / (Bsz * Hsz);
    if (nchunks < 1) nchunks = 1;
    dim3 grid(Hsz / 32, Bsz / BM);   // 32 x 64 = 2048 CTAs
    lstm_gemm_fused<<<grid, 256, SMEM_BYTES>>>(c_t, bf, bi, bc, bo,
                                               (float*)d_out, nchunks);
}